// round 2
// baseline (speedup 1.0000x reference)
#include <cuda_runtime.h>

#define BB 16
#define DD 32
#define CC 768
#define NHH 8
#define NOO 24
#define HWG 64
#define NPAIR (NHH*NOO)   // 192
#define H1 512
#define H2 256
#define H3 117
#define MT 12             // pair rows per block in MLP kernel (192 % 12 == 0)

// Scratch (device globals -- allocation-free)
__device__ float g_pooled[BB*DD*CC];     // 1.5 MB
__device__ float g_U[BB*DD*H1];          // 1 MB
__device__ int   g_hrow[BB*NHH];
__device__ int   g_orow[BB*NOO];

// ---------------------------------------------------------------------------
// Kernel 1: ROI mean pooling. 1 block per (b,d); 192 threads, float4 channels.
// ---------------------------------------------------------------------------
__global__ __launch_bounds__(192) void pool_kernel(
    const float* __restrict__ feat, const float* __restrict__ boxes)
{
    int bd = blockIdx.x;            // 0..511
    int b = bd >> 5;
    const float* box = boxes + bd * 4;
    float cx = box[0], cy = box[1], bw = box[2], bh = box[3];
    float hwd = __fmul_rn(bw, 0.5f);
    float hht = __fmul_rn(bh, 0.5f);
    // replicate jnp: floor(((c - w/2) * 896) / 14) in fp32, IEEE rn
    int x1 = (int)floorf(__fdiv_rn(__fmul_rn(__fsub_rn(cx, hwd), 896.0f), 14.0f));
    int y1 = (int)floorf(__fdiv_rn(__fmul_rn(__fsub_rn(cy, hht), 896.0f), 14.0f));
    int x2 = (int)floorf(__fdiv_rn(__fmul_rn(__fadd_rn(cx, hwd), 896.0f), 14.0f));
    int y2 = (int)floorf(__fdiv_rn(__fmul_rn(__fadd_rn(cy, hht), 896.0f), 14.0f));
    x1 = max(x1, 0); y1 = max(y1, 0);
    x2 = min(x2, HWG); y2 = min(y2, HWG);
    int nx = max(x2 - x1, 0), ny = max(y2 - y1, 0);
    float cnt = (float)(nx * ny);

    int t = threadIdx.x;            // 0..191 (float4 lane: channels 4t..4t+3)
    const float4* f4 = (const float4*)feat;
    float4 acc = make_float4(0.f, 0.f, 0.f, 0.f);
    for (int y = y1; y < y2; ++y) {
        int base = ((b * HWG + y) * HWG + x1) * (CC / 4) + t;
        for (int x = 0; x < nx; ++x, base += (CC / 4)) {
            float4 v = __ldg(&f4[base]);
            acc.x += v.x; acc.y += v.y; acc.z += v.z; acc.w += v.w;
        }
    }
    float4 o;
    o.x = acc.x / cnt; o.y = acc.y / cnt; o.z = acc.z / cnt; o.w = acc.w / cnt;
    ((float4*)g_pooled)[bd * (CC / 4) + t] = o;
}

// ---------------------------------------------------------------------------
// Kernel 2: per-batch stable descending argsort ranks (scatter rows).
// ---------------------------------------------------------------------------
__global__ __launch_bounds__(512) void sort_kernel(const float* __restrict__ scores)
{
    __shared__ float s[BB*DD];
    int t = threadIdx.x;            // 0..511
    s[t] = scores[t];
    __syncthreads();
    int b = t >> 5, d = t & 31;
    float v = s[t];
    if (d < NHH) {
        int r = 0;
        for (int j = 0; j < NHH; ++j) {
            float u = s[b*32 + j];
            r += (u > v) || (u == v && j < d);
        }
        g_hrow[b*NHH + r] = t;       // = b*32 + d (row in pooled/U)
    } else {
        int r = 0;
        for (int j = NHH; j < DD; ++j) {
            float u = s[b*32 + j];
            r += (u > v) || (u == v && j < d);
        }
        g_orow[b*NOO + r] = t;
    }
}

// ---------------------------------------------------------------------------
// Kernel 3: U = pooled @ w1_half  (half selected by d<8 vs d>=8).
// Grid (64 row-tiles of 8, 4 col-tiles of 128), 128 threads.
// Transposed smem As[k][r] so the inner loop is 2x LDS.128 broadcast + 8 FMA.
// ---------------------------------------------------------------------------
__global__ __launch_bounds__(128) void gemm1_kernel(const float* __restrict__ w1)
{
    __shared__ float As[CC * 8];    // 24 KB, layout [k][r]
    int r0 = blockIdx.x * 8;        // global row base (b*32+d)
    for (int idx = threadIdx.x; idx < 8 * CC; idx += 128) {
        int r = idx / CC, k = idx - r * CC;
        As[k * 8 + r] = g_pooled[(r0 + r) * CC + k];
    }
    __syncthreads();

    int off = ((r0 & 31) < NHH) ? 0 : CC;     // which half of w1
    int col = blockIdx.y * 128 + threadIdx.x;
    const float* wp = w1 + off * H1 + col;

    float acc[8];
#pragma unroll
    for (int r = 0; r < 8; ++r) acc[r] = 0.f;

#pragma unroll 4
    for (int k = 0; k < CC; ++k) {
        float wv = __ldg(&wp[k * H1]);
        float4 a0 = *(const float4*)&As[k * 8];
        float4 a1 = *(const float4*)&As[k * 8 + 4];
        acc[0] += a0.x * wv; acc[1] += a0.y * wv;
        acc[2] += a0.z * wv; acc[3] += a0.w * wv;
        acc[4] += a1.x * wv; acc[5] += a1.y * wv;
        acc[6] += a1.z * wv; acc[7] += a1.w * wv;
    }
#pragma unroll
    for (int r = 0; r < 8; ++r) g_U[(r0 + r) * H1 + col] = acc[r];
}

// ---------------------------------------------------------------------------
// Kernel 4: fused pair-build + relu(x1) + GEMM2 + relu + GEMM3 + bias.
// 256 blocks of MT=12 pairs, 256 threads. Transposed smem [k][m].
// ---------------------------------------------------------------------------
__global__ __launch_bounds__(256) void pair_mlp_kernel(
    const float* __restrict__ b1,
    const float* __restrict__ w2, const float* __restrict__ b2,
    const float* __restrict__ w3, const float* __restrict__ b3,
    float* __restrict__ out)
{
    __shared__ float x1t[H1 * MT];   // 24 KB, [n][m]
    __shared__ float x2t[H2 * MT];   // 12 KB, [k][m]
    __shared__ int hr[MT], orr[MT];

    int tile = blockIdx.x;           // 0..255
    int g0 = tile * MT;              // global pair base
    int t = threadIdx.x;

    if (t < MT) {
        int g = g0 + t;
        int b = g / NPAIR;
        int rem = g - b * NPAIR;
        int i = rem / NOO, j = rem - i * NOO;
        hr[t]  = g_hrow[b * NHH + i];
        orr[t] = g_orow[b * NOO + j];
    }
    __syncthreads();

    // Phase 1: x1t[n][m] = relu(U[hrow][n] + U[orow][n] + b1[n])
    for (int idx = t; idx < MT * H1; idx += 256) {
        int m = idx >> 9, n = idx & (H1 - 1);
        float v = g_U[hr[m] * H1 + n] + g_U[orr[m] * H1 + n] + __ldg(&b1[n]);
        x1t[n * MT + m] = fmaxf(v, 0.f);
    }
    __syncthreads();

    // Phase 2: x2[m][t] = relu(sum_k x1[m][k] * w2[k][t] + b2[t]); t = col
    float acc[MT];
#pragma unroll
    for (int m = 0; m < MT; ++m) acc[m] = 0.f;

#pragma unroll 2
    for (int k = 0; k < H1; ++k) {
        float wv = __ldg(&w2[k * H2 + t]);
        float4 a0 = *(const float4*)&x1t[k * MT];
        float4 a1 = *(const float4*)&x1t[k * MT + 4];
        float4 a2 = *(const float4*)&x1t[k * MT + 8];
        acc[0]  += a0.x * wv; acc[1]  += a0.y * wv;
        acc[2]  += a0.z * wv; acc[3]  += a0.w * wv;
        acc[4]  += a1.x * wv; acc[5]  += a1.y * wv;
        acc[6]  += a1.z * wv; acc[7]  += a1.w * wv;
        acc[8]  += a2.x * wv; acc[9]  += a2.y * wv;
        acc[10] += a2.z * wv; acc[11] += a2.w * wv;
    }
    {
        float bb = __ldg(&b2[t]);
#pragma unroll
        for (int m = 0; m < MT; ++m)
            x2t[t * MT + m] = fmaxf(acc[m] + bb, 0.f);
    }
    __syncthreads();

    // Phase 3: out[m][o] = sum_k x2[m][k] * w3[k][o] + b3[o]; threads o<117
    if (t < H3) {
        float a3[MT];
#pragma unroll
        for (int m = 0; m < MT; ++m) a3[m] = 0.f;
        for (int k = 0; k < H2; ++k) {
            float wv = __ldg(&w3[k * H3 + t]);
            float4 a0 = *(const float4*)&x2t[k * MT];
            float4 a1 = *(const float4*)&x2t[k * MT + 4];
            float4 a2 = *(const float4*)&x2t[k * MT + 8];
            a3[0]  += a0.x * wv; a3[1]  += a0.y * wv;
            a3[2]  += a0.z * wv; a3[3]  += a0.w * wv;
            a3[4]  += a1.x * wv; a3[5]  += a1.y * wv;
            a3[6]  += a1.z * wv; a3[7]  += a1.w * wv;
            a3[8]  += a2.x * wv; a3[9]  += a2.y * wv;
            a3[10] += a2.z * wv; a3[11] += a2.w * wv;
        }
        float bo = __ldg(&b3[t]);
#pragma unroll
        for (int m = 0; m < MT; ++m)
            out[(g0 + m) * H3 + t] = a3[m] + bo;
    }
}

// ---------------------------------------------------------------------------
extern "C" void kernel_launch(void* const* d_in, const int* in_sizes, int n_in,
                              void* d_out, int out_size)
{
    const float* features = (const float*)d_in[0];
    const float* boxes    = (const float*)d_in[1];
    const float* scores   = (const float*)d_in[2];
    const float* w1       = (const float*)d_in[3];
    const float* b1       = (const float*)d_in[4];
    const float* w2       = (const float*)d_in[5];
    const float* b2       = (const float*)d_in[6];
    const float* w3       = (const float*)d_in[7];
    const float* b3       = (const float*)d_in[8];
    // d_in[9] = labels (unused by reference output)
    float* out = (float*)d_out;

    pool_kernel<<<BB * DD, 192>>>(features, boxes);
    sort_kernel<<<1, BB * DD>>>(scores);
    dim3 g1(BB * DD / 8, H1 / 128);
    gemm1_kernel<<<g1, 128>>>(w1);
    pair_mlp_kernel<<<(BB * NPAIR) / MT, 256>>>(b1, w2, b2, w3, b3, out);
}

// round 3
// speedup vs baseline: 1.6527x; 1.6527x over previous
#include <cuda_runtime.h>

#define BB 16
#define DD 32
#define CC 768
#define NHH 8
#define NOO 24
#define HWG 64
#define NPAIR (NHH*NOO)   // 192
#define H1 512
#define H2 256
#define H3 117
#define MT 12             // pair rows per block in MLP kernel (192 % 12 == 0)

// Scratch (device globals -- allocation-free)
__device__ float g_pooled[BB*DD*CC];     // 1.5 MB
__device__ float g_U[BB*DD*H1];          // 1 MB
__device__ int   g_hrow[BB*NHH];
__device__ int   g_orow[BB*NOO];

// ---------------------------------------------------------------------------
// Packed fp32x2 helpers (sm_103a FFMA2 -- PTX-only)
// ---------------------------------------------------------------------------
__device__ __forceinline__ void fma2(unsigned long long& d,
                                     unsigned long long a,
                                     unsigned long long b) {
    asm("fma.rn.f32x2 %0, %1, %2, %0;" : "+l"(d) : "l"(a), "l"(b));
}
__device__ __forceinline__ unsigned long long bcast2(float v) {
    unsigned long long r;
    asm("mov.b64 %0, {%1, %1};" : "=l"(r) : "r"(__float_as_uint(v)));
    return r;
}
__device__ __forceinline__ float2 unpack2(unsigned long long v) {
    unsigned lo, hi;
    asm("mov.b64 {%0, %1}, %2;" : "=r"(lo), "=r"(hi) : "l"(v));
    return make_float2(__uint_as_float(lo), __uint_as_float(hi));
}

// ---------------------------------------------------------------------------
// Kernel 1: ROI mean pooling. 1 block per (b,d); 192 threads, float4 channels.
// ---------------------------------------------------------------------------
__global__ __launch_bounds__(192) void pool_kernel(
    const float* __restrict__ feat, const float* __restrict__ boxes)
{
    int bd = blockIdx.x;            // 0..511
    int b = bd >> 5;
    const float* box = boxes + bd * 4;
    float cx = box[0], cy = box[1], bw = box[2], bh = box[3];
    float hwd = __fmul_rn(bw, 0.5f);
    float hht = __fmul_rn(bh, 0.5f);
    // replicate jnp: floor(((c - w/2) * 896) / 14) in fp32, IEEE rn
    int x1 = (int)floorf(__fdiv_rn(__fmul_rn(__fsub_rn(cx, hwd), 896.0f), 14.0f));
    int y1 = (int)floorf(__fdiv_rn(__fmul_rn(__fsub_rn(cy, hht), 896.0f), 14.0f));
    int x2 = (int)floorf(__fdiv_rn(__fmul_rn(__fadd_rn(cx, hwd), 896.0f), 14.0f));
    int y2 = (int)floorf(__fdiv_rn(__fmul_rn(__fadd_rn(cy, hht), 896.0f), 14.0f));
    x1 = max(x1, 0); y1 = max(y1, 0);
    x2 = min(x2, HWG); y2 = min(y2, HWG);
    int nx = max(x2 - x1, 0), ny = max(y2 - y1, 0);
    float inv = 1.0f / (float)(nx * ny);

    int t = threadIdx.x;            // 0..191 (float4 lane: channels 4t..4t+3)
    const float4* f4 = (const float4*)feat;
    float4 acc = make_float4(0.f, 0.f, 0.f, 0.f);
    for (int y = y1; y < y2; ++y) {
        int base = ((b * HWG + y) * HWG + x1) * (CC / 4) + t;
#pragma unroll 4
        for (int x = 0; x < nx; ++x, base += (CC / 4)) {
            float4 v = __ldg(&f4[base]);
            acc.x += v.x; acc.y += v.y; acc.z += v.z; acc.w += v.w;
        }
    }
    float4 o;
    o.x = acc.x * inv; o.y = acc.y * inv; o.z = acc.z * inv; o.w = acc.w * inv;
    ((float4*)g_pooled)[bd * (CC / 4) + t] = o;
}

// ---------------------------------------------------------------------------
// Kernel 2: per-batch stable descending argsort ranks (scatter rows).
// ---------------------------------------------------------------------------
__global__ __launch_bounds__(512) void sort_kernel(const float* __restrict__ scores)
{
    __shared__ float s[BB*DD];
    int t = threadIdx.x;            // 0..511
    s[t] = scores[t];
    __syncthreads();
    int b = t >> 5, d = t & 31;
    float v = s[t];
    if (d < NHH) {
        int r = 0;
        for (int j = 0; j < NHH; ++j) {
            float u = s[b*32 + j];
            r += (u > v) || (u == v && j < d);
        }
        g_hrow[b*NHH + r] = t;       // = b*32 + d (row in pooled/U)
    } else {
        int r = 0;
        for (int j = NHH; j < DD; ++j) {
            float u = s[b*32 + j];
            r += (u > v) || (u == v && j < d);
        }
        g_orow[b*NOO + r] = t;
    }
}

// ---------------------------------------------------------------------------
// Kernel 3: U = pooled @ w1_half  (half selected by d<8 vs d>=8).
// Grid (64 row-tiles of 8, 4 col-tiles of 128), 128 threads.
// Prefetch 8 weight LDGs/iter; packed f32x2 FMA.
// ---------------------------------------------------------------------------
__global__ __launch_bounds__(128) void gemm1_kernel(const float* __restrict__ w1)
{
    __shared__ float As[CC * 8];    // 24 KB, layout [k][r], 32B-aligned rows
    int r0 = blockIdx.x * 8;        // global row base (b*32+d)
    for (int idx = threadIdx.x; idx < 8 * CC; idx += 128) {
        int r = idx / CC, k = idx - r * CC;
        As[k * 8 + r] = g_pooled[(r0 + r) * CC + k];
    }
    __syncthreads();

    int off = ((r0 & 31) < NHH) ? 0 : CC;     // which half of w1
    int col = blockIdx.y * 128 + threadIdx.x;
    const float* wp = w1 + off * H1 + col;

    unsigned long long acc[4];
#pragma unroll
    for (int p = 0; p < 4; ++p) acc[p] = 0ULL;

    for (int k0 = 0; k0 < CC; k0 += 8) {
        float w[8];
#pragma unroll
        for (int i = 0; i < 8; ++i) w[i] = __ldg(&wp[(k0 + i) * H1]);
#pragma unroll
        for (int i = 0; i < 8; ++i) {
            unsigned long long wpk = bcast2(w[i]);
            const ulonglong2* ap = (const ulonglong2*)&As[(k0 + i) * 8];
            ulonglong2 a0 = ap[0], a1 = ap[1];
            fma2(acc[0], a0.x, wpk); fma2(acc[1], a0.y, wpk);
            fma2(acc[2], a1.x, wpk); fma2(acc[3], a1.y, wpk);
        }
    }
#pragma unroll
    for (int p = 0; p < 4; ++p) {
        float2 f = unpack2(acc[p]);
        g_U[(r0 + 2*p)     * H1 + col] = f.x;
        g_U[(r0 + 2*p + 1) * H1 + col] = f.y;
    }
}

// ---------------------------------------------------------------------------
// Kernel 4: fused pair-build + relu(x1) + GEMM2 + relu + GEMM3 + bias.
// 256 blocks of MT=12 pairs, 256 threads. Transposed smem [k][m].
// ---------------------------------------------------------------------------
__global__ __launch_bounds__(256) void pair_mlp_kernel(
    const float* __restrict__ b1,
    const float* __restrict__ w2, const float* __restrict__ b2,
    const float* __restrict__ w3, const float* __restrict__ b3,
    float* __restrict__ out)
{
    __shared__ float x1t[H1 * MT];   // 24 KB, [n][m]  (also reused for GEMM3 partials)
    __shared__ float x2t[H2 * MT];   // 12 KB, [k][m]
    __shared__ int hr[MT], orr[MT];

    int tile = blockIdx.x;           // 0..255
    int g0 = tile * MT;              // global pair base
    int t = threadIdx.x;

    if (t < MT) {
        int g = g0 + t;
        int b = g / NPAIR;
        int rem = g - b * NPAIR;
        int i = rem / NOO, j = rem - i * NOO;
        hr[t]  = g_hrow[b * NHH + i];
        orr[t] = g_orow[b * NOO + j];
    }
    __syncthreads();

    // Phase 1: x1t[n][m] = relu(U[hrow][n] + U[orow][n] + b1[n])
    for (int idx = t; idx < MT * H1; idx += 256) {
        int m = idx >> 9, n = idx & (H1 - 1);
        float v = g_U[hr[m] * H1 + n] + g_U[orr[m] * H1 + n] + __ldg(&b1[n]);
        x1t[n * MT + m] = fmaxf(v, 0.f);
    }
    __syncthreads();

    // Phase 2: x2[m][t] = relu(sum_k x1[m][k] * w2[k][t] + b2[t]); t = col
    {
        const float* wp = w2 + t;
        unsigned long long acc[6];
#pragma unroll
        for (int p = 0; p < 6; ++p) acc[p] = 0ULL;

        for (int k0 = 0; k0 < H1; k0 += 8) {
            float w[8];
#pragma unroll
            for (int i = 0; i < 8; ++i) w[i] = __ldg(&wp[(k0 + i) * H2]);
#pragma unroll
            for (int i = 0; i < 8; ++i) {
                unsigned long long wpk = bcast2(w[i]);
                const ulonglong2* ap = (const ulonglong2*)&x1t[(k0 + i) * MT];
                ulonglong2 a0 = ap[0], a1 = ap[1], a2 = ap[2];
                fma2(acc[0], a0.x, wpk); fma2(acc[1], a0.y, wpk);
                fma2(acc[2], a1.x, wpk); fma2(acc[3], a1.y, wpk);
                fma2(acc[4], a2.x, wpk); fma2(acc[5], a2.y, wpk);
            }
        }
        float bb = __ldg(&b2[t]);
#pragma unroll
        for (int p = 0; p < 6; ++p) {
            float2 f = unpack2(acc[p]);
            x2t[t * MT + 2*p]     = fmaxf(f.x + bb, 0.f);
            x2t[t * MT + 2*p + 1] = fmaxf(f.y + bb, 0.f);
        }
    }
    __syncthreads();

    // Phase 3: out[m][o] = sum_k x2[m][k] * w3[k][o] + b3[o]
    // 234 active threads: split K into two halves of 128; half-1 partials via smem.
    float a3[MT];
    int half = (t >= H3) ? 1 : 0;
    int col  = t - half * H3;
    if (t < 2 * H3) {
        unsigned long long acc[6];
#pragma unroll
        for (int p = 0; p < 6; ++p) acc[p] = 0ULL;
        const float* wp3 = w3 + col;
        int kbeg = half * 128;
        for (int k0 = kbeg; k0 < kbeg + 128; k0 += 8) {
            float w[8];
#pragma unroll
            for (int i = 0; i < 8; ++i) w[i] = __ldg(&wp3[(k0 + i) * H3]);
#pragma unroll
            for (int i = 0; i < 8; ++i) {
                unsigned long long wpk = bcast2(w[i]);
                const ulonglong2* ap = (const ulonglong2*)&x2t[(k0 + i) * MT];
                ulonglong2 a0 = ap[0], a1 = ap[1], a2 = ap[2];
                fma2(acc[0], a0.x, wpk); fma2(acc[1], a0.y, wpk);
                fma2(acc[2], a1.x, wpk); fma2(acc[3], a1.y, wpk);
                fma2(acc[4], a2.x, wpk); fma2(acc[5], a2.y, wpk);
            }
        }
#pragma unroll
        for (int p = 0; p < 6; ++p) {
            float2 f = unpack2(acc[p]);
            a3[2*p] = f.x; a3[2*p + 1] = f.y;
        }
        if (half == 1) {
            // stash partials in reused x1t smem: part[col][m]
#pragma unroll
            for (int m = 0; m < MT; ++m) x1t[col * MT + m] = a3[m];
        }
    }
    __syncthreads();
    if (t < H3) {
        float bo = __ldg(&b3[t]);
#pragma unroll
        for (int m = 0; m < MT; ++m)
            out[(g0 + m) * H3 + t] = a3[m] + x1t[t * MT + m] + bo;
    }
}

// ---------------------------------------------------------------------------
extern "C" void kernel_launch(void* const* d_in, const int* in_sizes, int n_in,
                              void* d_out, int out_size)
{
    const float* features = (const float*)d_in[0];
    const float* boxes    = (const float*)d_in[1];
    const float* scores   = (const float*)d_in[2];
    const float* w1       = (const float*)d_in[3];
    const float* b1       = (const float*)d_in[4];
    const float* w2       = (const float*)d_in[5];
    const float* b2       = (const float*)d_in[6];
    const float* w3       = (const float*)d_in[7];
    const float* b3       = (const float*)d_in[8];
    // d_in[9] = labels (unused by reference output)
    float* out = (float*)d_out;

    pool_kernel<<<BB * DD, 192>>>(features, boxes);
    sort_kernel<<<1, BB * DD>>>(scores);
    dim3 g1(BB * DD / 8, H1 / 128);
    gemm1_kernel<<<g1, 128>>>(w1);
    pair_mlp_kernel<<<(BB * NPAIR) / MT, 256>>>(b1, w2, b2, w3, b3, out);
}

// round 4
// speedup vs baseline: 2.2867x; 1.3836x over previous
#include <cuda_runtime.h>

#define BB 16
#define DD 32
#define CC 768
#define NHH 8
#define NOO 24
#define HWG 64
#define NPAIR (NHH*NOO)   // 192
#define H1 512
#define H2 256
#define H3 117
#define MT 12             // pair rows per block in MLP kernel
#define YSPLIT 4

// Scratch (device globals -- allocation-free)
__device__ float g_part[BB*DD*YSPLIT*CC];   // 6.3 MB pooling partials
__device__ float g_invcnt[BB*DD];
__device__ float g_U[BB*DD*H1];             // 1 MB
__device__ int   g_hrow[BB*NHH];
__device__ int   g_orow[BB*NOO];

// ---------------------------------------------------------------------------
// Packed fp32x2 helpers (sm_103a FFMA2 -- PTX-only)
// ---------------------------------------------------------------------------
__device__ __forceinline__ void fma2(unsigned long long& d,
                                     unsigned long long a,
                                     unsigned long long b) {
    asm("fma.rn.f32x2 %0, %1, %2, %0;" : "+l"(d) : "l"(a), "l"(b));
}
__device__ __forceinline__ unsigned long long bcast2(float v) {
    unsigned long long r;
    asm("mov.b64 %0, {%1, %1};" : "=l"(r) : "r"(__float_as_uint(v)));
    return r;
}
__device__ __forceinline__ float2 unpack2(unsigned long long v) {
    unsigned lo, hi;
    asm("mov.b64 {%0, %1}, %2;" : "=r"(lo), "=r"(hi) : "l"(v));
    return make_float2(__uint_as_float(lo), __uint_as_float(hi));
}

// ---------------------------------------------------------------------------
// Kernel 1: ROI pooling partials (grid 2048 = bd*4 y-interleaved sub-blocks)
//           + sort absorbed into one extra block (blockIdx == 2048).
// ---------------------------------------------------------------------------
__global__ __launch_bounds__(192) void pool_kernel(
    const float* __restrict__ feat, const float* __restrict__ boxes,
    const float* __restrict__ scores)
{
    int blk = blockIdx.x;
    if (blk == BB * DD * YSPLIT) {
        // ---- sort block: per-batch stable descending ranks ----
        __shared__ float s[BB*DD];
        int t = threadIdx.x;
        for (int e = t; e < BB*DD; e += 192) s[e] = scores[e];
        __syncthreads();
        for (int e = t; e < BB*DD; e += 192) {
            int b = e >> 5, d = e & 31;
            float v = s[e];
            if (d < NHH) {
                int r = 0;
                for (int j = 0; j < NHH; ++j) {
                    float u = s[b*32 + j];
                    r += (u > v) || (u == v && j < d);
                }
                g_hrow[b*NHH + r] = e;
            } else {
                int r = 0;
                for (int j = NHH; j < DD; ++j) {
                    float u = s[b*32 + j];
                    r += (u > v) || (u == v && j < d);
                }
                g_orow[b*NOO + r] = e;
            }
        }
        return;
    }

    int bd = blk >> 2;              // 0..511
    int z  = blk & 3;               // y sub-slice
    int b  = bd >> 5;
    const float* box = boxes + bd * 4;
    float cx = box[0], cy = box[1], bw = box[2], bh = box[3];
    float hwd = __fmul_rn(bw, 0.5f);
    float hht = __fmul_rn(bh, 0.5f);
    int x1 = (int)floorf(__fdiv_rn(__fmul_rn(__fsub_rn(cx, hwd), 896.0f), 14.0f));
    int y1 = (int)floorf(__fdiv_rn(__fmul_rn(__fsub_rn(cy, hht), 896.0f), 14.0f));
    int x2 = (int)floorf(__fdiv_rn(__fmul_rn(__fadd_rn(cx, hwd), 896.0f), 14.0f));
    int y2 = (int)floorf(__fdiv_rn(__fmul_rn(__fadd_rn(cy, hht), 896.0f), 14.0f));
    x1 = max(x1, 0); y1 = max(y1, 0);
    x2 = min(x2, HWG); y2 = min(y2, HWG);
    int nx = max(x2 - x1, 0), ny = max(y2 - y1, 0);

    int t = threadIdx.x;            // channel float4 lane
    const float4* f4 = (const float4*)feat;
    float4 acc = make_float4(0.f, 0.f, 0.f, 0.f);
    for (int y = y1 + z; y < y2; y += YSPLIT) {
        int base = ((b * HWG + y) * HWG + x1) * (CC / 4) + t;
#pragma unroll 4
        for (int x = 0; x < nx; ++x, base += (CC / 4)) {
            float4 v = __ldg(&f4[base]);
            acc.x += v.x; acc.y += v.y; acc.z += v.z; acc.w += v.w;
        }
    }
    ((float4*)g_part)[(bd * YSPLIT + z) * (CC / 4) + t] = acc;
    if (z == 0 && t == 0)
        g_invcnt[bd] = 1.0f / (float)(nx * ny);
}

// ---------------------------------------------------------------------------
// Kernel 2: U = pooled @ w1_half. Grid (64, 4), 256 threads.
// Partial-reduce + mean folded into the smem load. Split-K halves + smem
// reduce; double-buffered weight registers.
// ---------------------------------------------------------------------------
__global__ __launch_bounds__(256) void gemm1_kernel(const float* __restrict__ w1)
{
    __shared__ float As[CC * 8];       // 24 KB, [k][r]
    __shared__ float red[128 * 8];     // 4 KB split-K partials
    int r0 = blockIdx.x * 8;
    int t = threadIdx.x;

    for (int idx = t; idx < 8 * CC; idx += 256) {
        int r = idx / CC, k = idx - r * CC;
        int bd = r0 + r;
        const float* p = g_part + (bd * YSPLIT) * CC + k;
        float v = (p[0] + p[CC] + p[2*CC] + p[3*CC]) * __ldg(&g_invcnt[bd]);
        As[k * 8 + r] = v;
    }
    __syncthreads();

    int half = t >> 7;                 // 0/1
    int lt   = t & 127;
    int col  = blockIdx.y * 128 + lt;
    int off  = ((r0 & 31) < NHH) ? 0 : CC;
    const float* wp = w1 + off * H1 + col;
    int kb = half * (CC / 2);          // 0 or 384

    unsigned long long acc[4];
#pragma unroll
    for (int p = 0; p < 4; ++p) acc[p] = 0ULL;

    float wcur[8];
#pragma unroll
    for (int i = 0; i < 8; ++i) wcur[i] = __ldg(&wp[(kb + i) * H1]);

    for (int k0 = kb; k0 < kb + CC/2; k0 += 8) {
        float wnxt[8];
        int kn = (k0 + 8 < kb + CC/2) ? (k0 + 8) : kb;
#pragma unroll
        for (int i = 0; i < 8; ++i) wnxt[i] = __ldg(&wp[(kn + i) * H1]);
#pragma unroll
        for (int i = 0; i < 8; ++i) {
            unsigned long long wpk = bcast2(wcur[i]);
            const ulonglong2* ap = (const ulonglong2*)&As[(k0 + i) * 8];
            ulonglong2 a0 = ap[0], a1 = ap[1];
            fma2(acc[0], a0.x, wpk); fma2(acc[1], a0.y, wpk);
            fma2(acc[2], a1.x, wpk); fma2(acc[3], a1.y, wpk);
        }
#pragma unroll
        for (int i = 0; i < 8; ++i) wcur[i] = wnxt[i];
    }

    if (half == 1) {
#pragma unroll
        for (int p = 0; p < 4; ++p) {
            float2 f = unpack2(acc[p]);
            red[lt * 8 + 2*p]     = f.x;
            red[lt * 8 + 2*p + 1] = f.y;
        }
    }
    __syncthreads();
    if (half == 0) {
#pragma unroll
        for (int p = 0; p < 4; ++p) {
            float2 f = unpack2(acc[p]);
            g_U[(r0 + 2*p)     * H1 + col] = f.x + red[lt * 8 + 2*p];
            g_U[(r0 + 2*p + 1) * H1 + col] = f.y + red[lt * 8 + 2*p + 1];
        }
    }
}

// ---------------------------------------------------------------------------
// Kernel 3: fused pair-build + relu(x1) + GEMM2 + relu + GEMM3 + bias.
// 256 blocks of MT=12 pairs, 256 threads. Double-buffered weight regs.
// ---------------------------------------------------------------------------
__global__ __launch_bounds__(256) void pair_mlp_kernel(
    const float* __restrict__ b1,
    const float* __restrict__ w2, const float* __restrict__ b2,
    const float* __restrict__ w3, const float* __restrict__ b3,
    float* __restrict__ out)
{
    __shared__ float x1t[H1 * MT];   // 24 KB, [n][m] (reused for GEMM3 partials)
    __shared__ float x2t[H2 * MT];   // 12 KB, [k][m]
    __shared__ int hr[MT], orr[MT];

    int g0 = blockIdx.x * MT;
    int t = threadIdx.x;

    if (t < MT) {
        int g = g0 + t;
        int b = g / NPAIR;
        int rem = g - b * NPAIR;
        int i = rem / NOO, j = rem - i * NOO;
        hr[t]  = g_hrow[b * NHH + i];
        orr[t] = g_orow[b * NOO + j];
    }
    __syncthreads();

    // Phase 1: x1t[n][m] = relu(U[hr][n] + U[orr][n] + b1[n]) -- float4 loads
    for (int idx = t; idx < MT * (H1/4); idx += 256) {
        int m = idx / (H1/4), n4 = idx - m * (H1/4);
        float4 uh = __ldg((const float4*)&g_U[hr[m]  * H1 + n4*4]);
        float4 uo = __ldg((const float4*)&g_U[orr[m] * H1 + n4*4]);
        float4 bb = __ldg((const float4*)&b1[n4*4]);
        x1t[(n4*4+0) * MT + m] = fmaxf(uh.x + uo.x + bb.x, 0.f);
        x1t[(n4*4+1) * MT + m] = fmaxf(uh.y + uo.y + bb.y, 0.f);
        x1t[(n4*4+2) * MT + m] = fmaxf(uh.z + uo.z + bb.z, 0.f);
        x1t[(n4*4+3) * MT + m] = fmaxf(uh.w + uo.w + bb.w, 0.f);
    }
    __syncthreads();

    // Phase 2: x2[m][t] = relu(x1 @ w2 + b2); thread t = output column
    {
        const float* wp = w2 + t;
        unsigned long long acc[6];
#pragma unroll
        for (int p = 0; p < 6; ++p) acc[p] = 0ULL;

        float wcur[8];
#pragma unroll
        for (int i = 0; i < 8; ++i) wcur[i] = __ldg(&wp[i * H2]);

        for (int k0 = 0; k0 < H1; k0 += 8) {
            float wnxt[8];
            int kn = (k0 + 8 < H1) ? (k0 + 8) : 0;
#pragma unroll
            for (int i = 0; i < 8; ++i) wnxt[i] = __ldg(&wp[(kn + i) * H2]);
#pragma unroll
            for (int i = 0; i < 8; ++i) {
                unsigned long long wpk = bcast2(wcur[i]);
                const ulonglong2* ap = (const ulonglong2*)&x1t[(k0 + i) * MT];
                ulonglong2 a0 = ap[0], a1 = ap[1], a2 = ap[2];
                fma2(acc[0], a0.x, wpk); fma2(acc[1], a0.y, wpk);
                fma2(acc[2], a1.x, wpk); fma2(acc[3], a1.y, wpk);
                fma2(acc[4], a2.x, wpk); fma2(acc[5], a2.y, wpk);
            }
#pragma unroll
            for (int i = 0; i < 8; ++i) wcur[i] = wnxt[i];
        }
        float bb = __ldg(&b2[t]);
#pragma unroll
        for (int p = 0; p < 6; ++p) {
            float2 f = unpack2(acc[p]);
            x2t[t * MT + 2*p]     = fmaxf(f.x + bb, 0.f);
            x2t[t * MT + 2*p + 1] = fmaxf(f.y + bb, 0.f);
        }
    }
    __syncthreads();

    // Phase 3: out = x2 @ w3 + b3. 234 threads: split-K halves, smem reduce.
    float a3[MT];
    int half = (t >= H3) ? 1 : 0;
    int col  = t - half * H3;
    if (t < 2 * H3) {
        unsigned long long acc[6];
#pragma unroll
        for (int p = 0; p < 6; ++p) acc[p] = 0ULL;
        const float* wp3 = w3 + col;
        int kbeg = half * (H2/2);

        float wcur[8];
#pragma unroll
        for (int i = 0; i < 8; ++i) wcur[i] = __ldg(&wp3[(kbeg + i) * H3]);

        for (int k0 = kbeg; k0 < kbeg + H2/2; k0 += 8) {
            float wnxt[8];
            int kn = (k0 + 8 < kbeg + H2/2) ? (k0 + 8) : kbeg;
#pragma unroll
            for (int i = 0; i < 8; ++i) wnxt[i] = __ldg(&wp3[(kn + i) * H3]);
#pragma unroll
            for (int i = 0; i < 8; ++i) {
                unsigned long long wpk = bcast2(wcur[i]);
                const ulonglong2* ap = (const ulonglong2*)&x2t[(k0 + i) * MT];
                ulonglong2 a0 = ap[0], a1 = ap[1], a2 = ap[2];
                fma2(acc[0], a0.x, wpk); fma2(acc[1], a0.y, wpk);
                fma2(acc[2], a1.x, wpk); fma2(acc[3], a1.y, wpk);
                fma2(acc[4], a2.x, wpk); fma2(acc[5], a2.y, wpk);
            }
#pragma unroll
            for (int i = 0; i < 8; ++i) wcur[i] = wnxt[i];
        }
#pragma unroll
        for (int p = 0; p < 6; ++p) {
            float2 f = unpack2(acc[p]);
            a3[2*p] = f.x; a3[2*p + 1] = f.y;
        }
        if (half == 1) {
#pragma unroll
            for (int m = 0; m < MT; ++m) x1t[col * MT + m] = a3[m];
        }
    }
    __syncthreads();
    if (t < H3) {
        float bo = __ldg(&b3[t]);
#pragma unroll
        for (int m = 0; m < MT; ++m)
            out[(g0 + m) * H3 + t] = a3[m] + x1t[t * MT + m] + bo;
    }
}

// ---------------------------------------------------------------------------
extern "C" void kernel_launch(void* const* d_in, const int* in_sizes, int n_in,
                              void* d_out, int out_size)
{
    const float* features = (const float*)d_in[0];
    const float* boxes    = (const float*)d_in[1];
    const float* scores   = (const float*)d_in[2];
    const float* w1       = (const float*)d_in[3];
    const float* b1       = (const float*)d_in[4];
    const float* w2       = (const float*)d_in[5];
    const float* b2       = (const float*)d_in[6];
    const float* w3       = (const float*)d_in[7];
    const float* b3       = (const float*)d_in[8];
    float* out = (float*)d_out;

    pool_kernel<<<BB * DD * YSPLIT + 1, 192>>>(features, boxes, scores);
    dim3 g1(BB * DD / 8, H1 / 128);
    gemm1_kernel<<<g1, 256>>>(w1);
    pair_mlp_kernel<<<(BB * NPAIR) / MT, 256>>>(b1, w2, b2, w3, b3, out);
}

// round 5
// speedup vs baseline: 2.6986x; 1.1801x over previous
#include <cuda_runtime.h>

#define BB 16
#define DD 32
#define CC 768
#define NHH 8
#define NOO 24
#define HWG 64
#define NPAIR (NHH*NOO)   // 192
#define H1 512
#define H2 256
#define H3 117
#define MT 12             // pair rows per block in MLP kernel
#define YSPLIT 4

// Scratch (device globals -- allocation-free)
__device__ float g_part[BB*DD*YSPLIT*CC];   // 6.3 MB pooling partials
__device__ float g_invcnt[BB*DD];
__device__ float g_U[BB*DD*H1];             // 1 MB
__device__ int   g_hrow[BB*NHH];
__device__ int   g_orow[BB*NOO];

// ---------------------------------------------------------------------------
// Packed fp32x2 helpers (sm_103a FFMA2 -- PTX-only)
// ---------------------------------------------------------------------------
__device__ __forceinline__ void fma2(unsigned long long& d,
                                     unsigned long long a,
                                     unsigned long long b) {
    asm("fma.rn.f32x2 %0, %1, %2, %0;" : "+l"(d) : "l"(a), "l"(b));
}
__device__ __forceinline__ unsigned long long bcast2(float v) {
    unsigned long long r;
    asm("mov.b64 %0, {%1, %1};" : "=l"(r) : "r"(__float_as_uint(v)));
    return r;
}
__device__ __forceinline__ float2 unpack2(unsigned long long v) {
    unsigned lo, hi;
    asm("mov.b64 {%0, %1}, %2;" : "=r"(lo), "=r"(hi) : "l"(v));
    return make_float2(__uint_as_float(lo), __uint_as_float(hi));
}

// ---------------------------------------------------------------------------
// Kernel 1: ROI pooling partials (grid 2048 = bd*4 y-interleaved sub-blocks)
//           + sort absorbed into one extra block (blockIdx == 2048).
// ---------------------------------------------------------------------------
__global__ __launch_bounds__(192) void pool_kernel(
    const float* __restrict__ feat, const float* __restrict__ boxes,
    const float* __restrict__ scores)
{
    int blk = blockIdx.x;
    if (blk == BB * DD * YSPLIT) {
        // ---- sort block: per-batch stable descending ranks ----
        __shared__ float s[BB*DD];
        int t = threadIdx.x;
        for (int e = t; e < BB*DD; e += 192) s[e] = scores[e];
        __syncthreads();
        for (int e = t; e < BB*DD; e += 192) {
            int b = e >> 5, d = e & 31;
            float v = s[e];
            if (d < NHH) {
                int r = 0;
                for (int j = 0; j < NHH; ++j) {
                    float u = s[b*32 + j];
                    r += (u > v) || (u == v && j < d);
                }
                g_hrow[b*NHH + r] = e;
            } else {
                int r = 0;
                for (int j = NHH; j < DD; ++j) {
                    float u = s[b*32 + j];
                    r += (u > v) || (u == v && j < d);
                }
                g_orow[b*NOO + r] = e;
            }
        }
        return;
    }

    int bd = blk >> 2;              // 0..511
    int z  = blk & 3;               // y sub-slice
    int b  = bd >> 5;
    const float* box = boxes + bd * 4;
    float cx = box[0], cy = box[1], bw = box[2], bh = box[3];
    float hwd = __fmul_rn(bw, 0.5f);
    float hht = __fmul_rn(bh, 0.5f);
    int x1 = (int)floorf(__fdiv_rn(__fmul_rn(__fsub_rn(cx, hwd), 896.0f), 14.0f));
    int y1 = (int)floorf(__fdiv_rn(__fmul_rn(__fsub_rn(cy, hht), 896.0f), 14.0f));
    int x2 = (int)floorf(__fdiv_rn(__fmul_rn(__fadd_rn(cx, hwd), 896.0f), 14.0f));
    int y2 = (int)floorf(__fdiv_rn(__fmul_rn(__fadd_rn(cy, hht), 896.0f), 14.0f));
    x1 = max(x1, 0); y1 = max(y1, 0);
    x2 = min(x2, HWG); y2 = min(y2, HWG);
    int nx = max(x2 - x1, 0), ny = max(y2 - y1, 0);

    int t = threadIdx.x;            // channel float4 lane
    const float4* f4 = (const float4*)feat;
    // Two independent accumulators -> 2x shorter FADD chains, more loads in flight
    float4 acc0 = make_float4(0.f, 0.f, 0.f, 0.f);
    float4 acc1 = make_float4(0.f, 0.f, 0.f, 0.f);
    for (int y = y1 + z; y < y2; y += YSPLIT) {
        int base = ((b * HWG + y) * HWG + x1) * (CC / 4) + t;
        int x = 0;
#pragma unroll 2
        for (; x + 2 <= nx; x += 2, base += 2 * (CC / 4)) {
            float4 v0 = __ldg(&f4[base]);
            float4 v1 = __ldg(&f4[base + (CC / 4)]);
            acc0.x += v0.x; acc0.y += v0.y; acc0.z += v0.z; acc0.w += v0.w;
            acc1.x += v1.x; acc1.y += v1.y; acc1.z += v1.z; acc1.w += v1.w;
        }
        if (x < nx) {
            float4 v0 = __ldg(&f4[base]);
            acc0.x += v0.x; acc0.y += v0.y; acc0.z += v0.z; acc0.w += v0.w;
        }
    }
    acc0.x += acc1.x; acc0.y += acc1.y; acc0.z += acc1.z; acc0.w += acc1.w;
    ((float4*)g_part)[(bd * YSPLIT + z) * (CC / 4) + t] = acc0;
    if (z == 0 && t == 0)
        g_invcnt[bd] = 1.0f / (float)(nx * ny);
}

// ---------------------------------------------------------------------------
// Kernel 2: U = pooled @ w1_half. Grid (64, 4), 256 threads.
// Split-K halves + smem reduce; 16-k double-buffered weight registers.
// ---------------------------------------------------------------------------
__global__ __launch_bounds__(256) void gemm1_kernel(const float* __restrict__ w1)
{
    __shared__ float As[CC * 8];       // 24 KB, [k][r]
    __shared__ float red[128 * 8];     // 4 KB split-K partials
    int r0 = blockIdx.x * 8;
    int t = threadIdx.x;

    for (int idx = t; idx < 8 * CC; idx += 256) {
        int r = idx / CC, k = idx - r * CC;
        int bd = r0 + r;
        const float* p = g_part + (bd * YSPLIT) * CC + k;
        float v = (p[0] + p[CC] + p[2*CC] + p[3*CC]) * __ldg(&g_invcnt[bd]);
        As[k * 8 + r] = v;
    }
    __syncthreads();

    int half = t >> 7;                 // 0/1
    int lt   = t & 127;
    int col  = blockIdx.y * 128 + lt;
    int off  = ((r0 & 31) < NHH) ? 0 : CC;
    const float* wp = w1 + off * H1 + col;
    int kb = half * (CC / 2);          // 0 or 384

    unsigned long long acc[4];
#pragma unroll
    for (int p = 0; p < 4; ++p) acc[p] = 0ULL;

    float wcur[16];
#pragma unroll
    for (int i = 0; i < 16; ++i) wcur[i] = __ldg(&wp[(kb + i) * H1]);

    for (int k0 = kb; k0 < kb + CC/2; k0 += 16) {
        float wnxt[16];
        int kn = (k0 + 16 < kb + CC/2) ? (k0 + 16) : kb;
#pragma unroll
        for (int i = 0; i < 16; ++i) wnxt[i] = __ldg(&wp[(kn + i) * H1]);
#pragma unroll
        for (int i = 0; i < 16; ++i) {
            unsigned long long wpk = bcast2(wcur[i]);
            const ulonglong2* ap = (const ulonglong2*)&As[(k0 + i) * 8];
            ulonglong2 a0 = ap[0], a1 = ap[1];
            fma2(acc[0], a0.x, wpk); fma2(acc[1], a0.y, wpk);
            fma2(acc[2], a1.x, wpk); fma2(acc[3], a1.y, wpk);
        }
#pragma unroll
        for (int i = 0; i < 16; ++i) wcur[i] = wnxt[i];
    }

    if (half == 1) {
#pragma unroll
        for (int p = 0; p < 4; ++p) {
            float2 f = unpack2(acc[p]);
            red[lt * 8 + 2*p]     = f.x;
            red[lt * 8 + 2*p + 1] = f.y;
        }
    }
    __syncthreads();
    if (half == 0) {
#pragma unroll
        for (int p = 0; p < 4; ++p) {
            float2 f = unpack2(acc[p]);
            g_U[(r0 + 2*p)     * H1 + col] = f.x + red[lt * 8 + 2*p];
            g_U[(r0 + 2*p + 1) * H1 + col] = f.y + red[lt * 8 + 2*p + 1];
        }
    }
}

// ---------------------------------------------------------------------------
// Kernel 3: fused pair-build + relu(x1) + GEMM2 + relu + GEMM3 + bias.
// 256 blocks of MT=12 pairs, 256 threads. 16-k double-buffered weight regs.
// ---------------------------------------------------------------------------
__global__ __launch_bounds__(256) void pair_mlp_kernel(
    const float* __restrict__ b1,
    const float* __restrict__ w2, const float* __restrict__ b2,
    const float* __restrict__ w3, const float* __restrict__ b3,
    float* __restrict__ out)
{
    __shared__ float x1t[H1 * MT];   // 24 KB, [n][m] (reused for GEMM3 partials)
    __shared__ float x2t[H2 * MT];   // 12 KB, [k][m]
    __shared__ int hr[MT], orr[MT];

    int g0 = blockIdx.x * MT;
    int t = threadIdx.x;

    if (t < MT) {
        int g = g0 + t;
        int b = g / NPAIR;
        int rem = g - b * NPAIR;
        int i = rem / NOO, j = rem - i * NOO;
        hr[t]  = g_hrow[b * NHH + i];
        orr[t] = g_orow[b * NOO + j];
    }
    __syncthreads();

    // Phase 1: x1t[n][m] = relu(U[hr][n] + U[orr][n] + b1[n]) -- float4 loads
    for (int idx = t; idx < MT * (H1/4); idx += 256) {
        int m = idx / (H1/4), n4 = idx - m * (H1/4);
        float4 uh = __ldg((const float4*)&g_U[hr[m]  * H1 + n4*4]);
        float4 uo = __ldg((const float4*)&g_U[orr[m] * H1 + n4*4]);
        float4 bb = __ldg((const float4*)&b1[n4*4]);
        x1t[(n4*4+0) * MT + m] = fmaxf(uh.x + uo.x + bb.x, 0.f);
        x1t[(n4*4+1) * MT + m] = fmaxf(uh.y + uo.y + bb.y, 0.f);
        x1t[(n4*4+2) * MT + m] = fmaxf(uh.z + uo.z + bb.z, 0.f);
        x1t[(n4*4+3) * MT + m] = fmaxf(uh.w + uo.w + bb.w, 0.f);
    }
    __syncthreads();

    // Phase 2: x2[m][t] = relu(x1 @ w2 + b2); thread t = output column
    {
        const float* wp = w2 + t;
        unsigned long long acc[6];
#pragma unroll
        for (int p = 0; p < 6; ++p) acc[p] = 0ULL;

        float wcur[16];
#pragma unroll
        for (int i = 0; i < 16; ++i) wcur[i] = __ldg(&wp[i * H2]);

        for (int k0 = 0; k0 < H1; k0 += 16) {
            float wnxt[16];
            int kn = (k0 + 16 < H1) ? (k0 + 16) : 0;
#pragma unroll
            for (int i = 0; i < 16; ++i) wnxt[i] = __ldg(&wp[(kn + i) * H2]);
#pragma unroll
            for (int i = 0; i < 16; ++i) {
                unsigned long long wpk = bcast2(wcur[i]);
                const ulonglong2* ap = (const ulonglong2*)&x1t[(k0 + i) * MT];
                ulonglong2 a0 = ap[0], a1 = ap[1], a2 = ap[2];
                fma2(acc[0], a0.x, wpk); fma2(acc[1], a0.y, wpk);
                fma2(acc[2], a1.x, wpk); fma2(acc[3], a1.y, wpk);
                fma2(acc[4], a2.x, wpk); fma2(acc[5], a2.y, wpk);
            }
#pragma unroll
            for (int i = 0; i < 16; ++i) wcur[i] = wnxt[i];
        }
        float bb = __ldg(&b2[t]);
#pragma unroll
        for (int p = 0; p < 6; ++p) {
            float2 f = unpack2(acc[p]);
            float2 s;
            s.x = fmaxf(f.x + bb, 0.f);
            s.y = fmaxf(f.y + bb, 0.f);
            *(float2*)&x2t[t * MT + 2*p] = s;
        }
    }
    __syncthreads();

    // Phase 3: out = x2 @ w3 + b3. 234 threads: split-K halves, smem reduce.
    float a3[MT];
    int half = (t >= H3) ? 1 : 0;
    int col  = t - half * H3;
    if (t < 2 * H3) {
        unsigned long long acc[6];
#pragma unroll
        for (int p = 0; p < 6; ++p) acc[p] = 0ULL;
        const float* wp3 = w3 + col;
        int kbeg = half * (H2/2);

        float wcur[16];
#pragma unroll
        for (int i = 0; i < 16; ++i) wcur[i] = __ldg(&wp3[(kbeg + i) * H3]);

        for (int k0 = kbeg; k0 < kbeg + H2/2; k0 += 16) {
            float wnxt[16];
            int kn = (k0 + 16 < kbeg + H2/2) ? (k0 + 16) : kbeg;
#pragma unroll
            for (int i = 0; i < 16; ++i) wnxt[i] = __ldg(&wp3[(kn + i) * H3]);
#pragma unroll
            for (int i = 0; i < 16; ++i) {
                unsigned long long wpk = bcast2(wcur[i]);
                const ulonglong2* ap = (const ulonglong2*)&x2t[(k0 + i) * MT];
                ulonglong2 a0 = ap[0], a1 = ap[1], a2 = ap[2];
                fma2(acc[0], a0.x, wpk); fma2(acc[1], a0.y, wpk);
                fma2(acc[2], a1.x, wpk); fma2(acc[3], a1.y, wpk);
                fma2(acc[4], a2.x, wpk); fma2(acc[5], a2.y, wpk);
            }
#pragma unroll
            for (int i = 0; i < 16; ++i) wcur[i] = wnxt[i];
        }
#pragma unroll
        for (int p = 0; p < 6; ++p) {
            float2 f = unpack2(acc[p]);
            a3[2*p] = f.x; a3[2*p + 1] = f.y;
        }
        if (half == 1) {
#pragma unroll
            for (int m = 0; m < MT; ++m) x1t[col * MT + m] = a3[m];
        }
    }
    __syncthreads();
    if (t < H3) {
        float bo = __ldg(&b3[t]);
#pragma unroll
        for (int m = 0; m < MT; ++m)
            out[(g0 + m) * H3 + t] = a3[m] + x1t[t * MT + m] + bo;
    }
}

// ---------------------------------------------------------------------------
extern "C" void kernel_launch(void* const* d_in, const int* in_sizes, int n_in,
                              void* d_out, int out_size)
{
    const float* features = (const float*)d_in[0];
    const float* boxes    = (const float*)d_in[1];
    const float* scores   = (const float*)d_in[2];
    const float* w1       = (const float*)d_in[3];
    const float* b1       = (const float*)d_in[4];
    const float* w2       = (const float*)d_in[5];
    const float* b2       = (const float*)d_in[6];
    const float* w3       = (const float*)d_in[7];
    const float* b3       = (const float*)d_in[8];
    float* out = (float*)d_out;

    pool_kernel<<<BB * DD * YSPLIT + 1, 192>>>(features, boxes, scores);
    dim3 g1(BB * DD / 8, H1 / 128);
    gemm1_kernel<<<g1, 256>>>(w1);
    pair_mlp_kernel<<<(BB * NPAIR) / MT, 256>>>(b1, w2, b2, w3, b3, out);
}